// round 5
// baseline (speedup 1.0000x reference)
#include <cuda_runtime.h>
#include <cuda_bf16.h>
#include <mma.h>
#include <stdint.h>

using namespace nvcuda;

#define NN 100000
#define NE 1600000
#define DH 128
#define NTILES 782   // ceil(NN/128)

// ---- scratch (device globals; no allocation allowed) ----
__device__ int   g_deg[NN];
__device__ int   g_rowptr[NN + 1];
__device__ int   g_cursor[NN];
__device__ int   g_csr_src[NE];
__device__ float g_csr_w[NE];
__device__ __nv_bfloat16 g_agghi[NN * DH];
__device__ __nv_bfloat16 g_agglo[NN * DH];
__device__ __nv_bfloat16 g_s0hi[NN * DH];
__device__ __nv_bfloat16 g_s0lo[NN * DH];
__device__ __nv_bfloat16 g_s1hi[NN * DH];
__device__ __nv_bfloat16 g_s1lo[NN * DH];
__device__ float g_h1[NN * DH];
__device__ float g_h2[NN * DH];
__device__ __nv_bfloat16 g_whi[3 * 256 * 128];   // [layer][k][n] : k<128 Wrel, k>=128 Wroot
__device__ __nv_bfloat16 g_wlo[3 * 256 * 128];

// ============ small helpers ============
__device__ __forceinline__ uint32_t bfpack(__nv_bfloat16 a, __nv_bfloat16 b) {
    return (uint32_t)__bfloat16_as_ushort(a) | ((uint32_t)__bfloat16_as_ushort(b) << 16);
}
__device__ __forceinline__ void split_bf(float v, __nv_bfloat16& h, __nv_bfloat16& l) {
    h = __float2bfloat16_rn(v);
    l = __float2bfloat16_rn(v - __bfloat162float(h));
}

// ============ CSR build ============
__global__ void deg_count_kernel(const int* __restrict__ dst, int* __restrict__ deg) {
    int i = blockIdx.x * blockDim.x + threadIdx.x;
    if (i < NE) atomicAdd(&deg[dst[i]], 1);
}

__global__ void scan_kernel(const int* __restrict__ deg,
                            int* __restrict__ rowptr, int* __restrict__ cursor) {
    __shared__ int sdata[1024];
    __shared__ int carry;
    if (threadIdx.x == 0) carry = 0;
    __syncthreads();
    for (int base = 0; base < NN; base += 1024) {
        int i = base + (int)threadIdx.x;
        int v = (i < NN) ? deg[i] : 0;
        sdata[threadIdx.x] = v;
        __syncthreads();
        #pragma unroll
        for (int off = 1; off < 1024; off <<= 1) {
            int t = (threadIdx.x >= off) ? sdata[threadIdx.x - off] : 0;
            __syncthreads();
            sdata[threadIdx.x] += t;
            __syncthreads();
        }
        int excl = sdata[threadIdx.x] - v + carry;
        if (i < NN) { rowptr[i] = excl; cursor[i] = excl; }
        __syncthreads();
        if (threadIdx.x == 0) carry += sdata[1023];
        __syncthreads();
    }
    if (threadIdx.x == 0) rowptr[NN] = carry;
}

__global__ void fill_csr_kernel(const int* __restrict__ src, const int* __restrict__ dst,
                                const float* __restrict__ w, int* __restrict__ cursor,
                                int* __restrict__ csr_src, float* __restrict__ csr_w) {
    int e = blockIdx.x * blockDim.x + threadIdx.x;
    if (e < NE) {
        int d = dst[e];
        int p = atomicAdd(&cursor[d], 1);
        csr_src[p] = src[e];
        csr_w[p]   = w[e];
    }
}

// ============ input split / weight prep ============
__global__ void split_x_kernel(const float* __restrict__ x,
                               __nv_bfloat16* __restrict__ hi, __nv_bfloat16* __restrict__ lo) {
    int i = blockIdx.x * blockDim.x + threadIdx.x;
    if (i < NN * DH) {
        __nv_bfloat16 h, l;
        split_bf(x[i], h, l);
        hi[i] = h; lo[i] = l;
    }
}

// W[k][n]: k<128 -> Wrel[k][n], k>=128 -> Wroot[k-128][n]  (natural row-major stack)
__global__ void prep_w_kernel(const float* __restrict__ Wrel, const float* __restrict__ Wroot,
                              __nv_bfloat16* __restrict__ hi, __nv_bfloat16* __restrict__ lo) {
    int i = blockIdx.x * blockDim.x + threadIdx.x;
    if (i >= 256 * 128) return;
    int k = i >> 7;
    int n = i & 127;
    float v = (k < 128) ? Wrel[k * 128 + n] : Wroot[(k - 128) * 128 + n];
    __nv_bfloat16 h, l;
    split_bf(v, h, l);
    hi[i] = h; lo[i] = l;
}

// ============ aggregation: one warp per node, gather, mean fused, bf16-split output ============
__global__ void gather_agg_kernel(const float* __restrict__ xin,
                                  const int* __restrict__ rowptr,
                                  const int* __restrict__ csr_src,
                                  const float* __restrict__ csr_w,
                                  __nv_bfloat16* __restrict__ agghi,
                                  __nv_bfloat16* __restrict__ agglo) {
    unsigned gt = blockIdx.x * blockDim.x + threadIdx.x;
    unsigned node = gt >> 5;
    int lane = threadIdx.x & 31;
    if (node >= NN) return;
    int s0 = __ldg(rowptr + node);
    int s1 = __ldg(rowptr + node + 1);
    float4 acc = make_float4(0.f, 0.f, 0.f, 0.f);
    int e = s0;
    for (; e + 3 < s1; e += 4) {
        int   s_[4]; float w_[4];
        #pragma unroll
        for (int q = 0; q < 4; q++) { s_[q] = __ldg(csr_src + e + q); w_[q] = __ldg(csr_w + e + q); }
        float4 v_[4];
        #pragma unroll
        for (int q = 0; q < 4; q++)
            v_[q] = *reinterpret_cast<const float4*>(xin + (size_t)s_[q] * DH + lane * 4);
        #pragma unroll
        for (int q = 0; q < 4; q++) {
            acc.x = fmaf(w_[q], v_[q].x, acc.x); acc.y = fmaf(w_[q], v_[q].y, acc.y);
            acc.z = fmaf(w_[q], v_[q].z, acc.z); acc.w = fmaf(w_[q], v_[q].w, acc.w);
        }
    }
    for (; e < s1; e++) {
        int   sa = __ldg(csr_src + e);
        float wa = __ldg(csr_w + e);
        float4 va = *reinterpret_cast<const float4*>(xin + (size_t)sa * DH + lane * 4);
        acc.x = fmaf(wa, va.x, acc.x); acc.y = fmaf(wa, va.y, acc.y);
        acc.z = fmaf(wa, va.z, acc.z); acc.w = fmaf(wa, va.w, acc.w);
    }
    float di = (s1 > s0) ? 1.0f / (float)(s1 - s0) : 0.f;
    acc.x *= di; acc.y *= di; acc.z *= di; acc.w *= di;

    __nv_bfloat16 h0, l0, h1, l1, h2, l2, h3, l3;
    split_bf(acc.x, h0, l0); split_bf(acc.y, h1, l1);
    split_bf(acc.z, h2, l2); split_bf(acc.w, h3, l3);
    size_t off = (size_t)node * DH + lane * 4;
    *reinterpret_cast<uint2*>(agghi + off) = make_uint2(bfpack(h0, h1), bfpack(h2, h3));
    *reinterpret_cast<uint2*>(agglo + off) = make_uint2(bfpack(l0, l1), bfpack(l2, l3));
}

// ============ GEMM: out = relu([agg|x] @ [Wrel;Wroot] + b) via wmma bf16 3-product ============
// CTA: 128x128 tile, 256 threads (8 warps, 2x4). Warp tile 32x64.
// B (hi+lo) resident in smem (stride 136); A chunks (128x32, hi+lo, stride 40) double-buffered.
#define BSTR 136
#define ASTR 40
#define OFF_BIAS 0u
#define OFF_BH   512u
#define OFF_BL   (512u + 69632u)                  // 70144
#define OFF_A    (512u + 2u * 69632u)             // 139776 ; 4 * 10240 = 40960
#define GEMM_SMEM (512 + 2 * 69632 + 4 * 10240)   // 180736

__global__ void __launch_bounds__(256, 1) gemm_wmma_kernel(
    const __nv_bfloat16* __restrict__ agghi, const __nv_bfloat16* __restrict__ agglo,
    const __nv_bfloat16* __restrict__ xhi,   const __nv_bfloat16* __restrict__ xlo,
    const __nv_bfloat16* __restrict__ whi,   const __nv_bfloat16* __restrict__ wlo,
    const float* __restrict__ bias, float* __restrict__ hout,
    __nv_bfloat16* __restrict__ shi, __nv_bfloat16* __restrict__ slo, int write_split)
{
    extern __shared__ char smem[];
    float* sbias = reinterpret_cast<float*>(smem + OFF_BIAS);
    __nv_bfloat16* BH = reinterpret_cast<__nv_bfloat16*>(smem + OFF_BH);
    __nv_bfloat16* BL = reinterpret_cast<__nv_bfloat16*>(smem + OFF_BL);
    __nv_bfloat16* AH[2] = {reinterpret_cast<__nv_bfloat16*>(smem + OFF_A),
                            reinterpret_cast<__nv_bfloat16*>(smem + OFF_A + 20480u)};
    __nv_bfloat16* AL[2] = {reinterpret_cast<__nv_bfloat16*>(smem + OFF_A + 10240u),
                            reinterpret_cast<__nv_bfloat16*>(smem + OFF_A + 30720u)};

    const int tid = threadIdx.x;
    const int wid = tid >> 5;
    const int wm = wid >> 1;      // 0..3 -> rows 32*wm
    const int wn = wid & 1;       // 0..1 -> cols 64*wn
    const int row0 = blockIdx.x * 128;

    if (tid < 128) sbias[tid] = bias[tid];

    // load B hi+lo: [256][128] -> smem stride 136
    #pragma unroll
    for (int j = 0; j < 16; j++) {
        int f = tid + j * 256;          // 0..4095
        int r = f >> 4, c8 = f & 15;
        uint4 vh = *reinterpret_cast<const uint4*>(whi + (size_t)r * 128 + c8 * 8);
        uint4 vl = *reinterpret_cast<const uint4*>(wlo + (size_t)r * 128 + c8 * 8);
        *reinterpret_cast<uint4*>(BH + r * BSTR + c8 * 8) = vh;
        *reinterpret_cast<uint4*>(BL + r * BSTR + c8 * 8) = vl;
    }

    // A chunk loader: chunk c in [0,8): k-range c*32..c*32+31 of logical K=256
    uint4 ra_h[2], ra_l[2];
    auto ldgA = [&](int c) {
        const __nv_bfloat16* ph = (c < 4) ? agghi : xhi;
        const __nv_bfloat16* pl = (c < 4) ? agglo : xlo;
        const int k0 = (c & 3) * 32;
        #pragma unroll
        for (int j = 0; j < 2; j++) {
            int f = tid + j * 256;      // 0..511
            int r = f >> 2, kq = f & 3;
            int grow = row0 + r;
            uint4 vh = make_uint4(0, 0, 0, 0), vl = make_uint4(0, 0, 0, 0);
            if (grow < NN) {
                size_t go = (size_t)grow * DH + k0 + kq * 8;
                vh = *reinterpret_cast<const uint4*>(ph + go);
                vl = *reinterpret_cast<const uint4*>(pl + go);
            }
            ra_h[j] = vh; ra_l[j] = vl;
        }
    };
    auto stsA = [&](int b) {
        #pragma unroll
        for (int j = 0; j < 2; j++) {
            int f = tid + j * 256;
            int r = f >> 2, kq = f & 3;
            *reinterpret_cast<uint4*>(AH[b] + r * ASTR + kq * 8) = ra_h[j];
            *reinterpret_cast<uint4*>(AL[b] + r * ASTR + kq * 8) = ra_l[j];
        }
    };

    wmma::fragment<wmma::accumulator, 16, 16, 16, float> acc[2][4];
    #pragma unroll
    for (int i = 0; i < 2; i++)
        #pragma unroll
        for (int j = 0; j < 4; j++) wmma::fill_fragment(acc[i][j], 0.f);

    ldgA(0); stsA(0);
    __syncthreads();

    #pragma unroll 1
    for (int c = 0; c < 8; c++) {
        const int buf = c & 1;
        if (c < 7) ldgA(c + 1);

        #pragma unroll
        for (int kk = 0; kk < 2; kk++) {
            wmma::fragment<wmma::matrix_a, 16, 16, 16, __nv_bfloat16, wmma::row_major> fah[2], fal[2];
            wmma::fragment<wmma::matrix_b, 16, 16, 16, __nv_bfloat16, wmma::row_major> fbh[4], fbl[4];
            #pragma unroll
            for (int i = 0; i < 2; i++) {
                const __nv_bfloat16* pa = AH[buf] + (32 * wm + 16 * i) * ASTR + kk * 16;
                const __nv_bfloat16* qa = AL[buf] + (32 * wm + 16 * i) * ASTR + kk * 16;
                wmma::load_matrix_sync(fah[i], pa, ASTR);
                wmma::load_matrix_sync(fal[i], qa, ASTR);
            }
            const int krow = c * 32 + kk * 16;
            #pragma unroll
            for (int j = 0; j < 4; j++) {
                wmma::load_matrix_sync(fbh[j], BH + krow * BSTR + 64 * wn + 16 * j, BSTR);
                wmma::load_matrix_sync(fbl[j], BL + krow * BSTR + 64 * wn + 16 * j, BSTR);
            }
            #pragma unroll
            for (int i = 0; i < 2; i++)
                #pragma unroll
                for (int j = 0; j < 4; j++) {
                    wmma::mma_sync(acc[i][j], fah[i], fbh[j], acc[i][j]);
                    wmma::mma_sync(acc[i][j], fah[i], fbl[j], acc[i][j]);
                    wmma::mma_sync(acc[i][j], fal[i], fbh[j], acc[i][j]);
                }
        }

        if (c < 7) {
            stsA(buf ^ 1);
            __syncthreads();
        }
    }

    // epilogue: dump accs to smem scratch (reuse B region), then bias+relu+store
    __syncthreads();
    float* scr = reinterpret_cast<float*>(smem + OFF_BH);  // [128][132] f32 = 67584 B
    #pragma unroll
    for (int i = 0; i < 2; i++)
        #pragma unroll
        for (int j = 0; j < 4; j++)
            wmma::store_matrix_sync(scr + (32 * wm + 16 * i) * 132 + 64 * wn + 16 * j,
                                    acc[i][j], 132, wmma::mem_row_major);
    __syncthreads();

    {
        const int r = tid >> 1;             // 0..127
        const int half = tid & 1;           // 64 cols each
        const int row = row0 + r;
        if (row < NN) {
            const float* sr = scr + r * 132 + half * 64;
            const float* bb = sbias + half * 64;
            float* orow = hout + (size_t)row * DH + half * 64;
            #pragma unroll
            for (int j = 0; j < 64; j += 4) {
                float v0 = fmaxf(sr[j]     + bb[j],     0.f);
                float v1 = fmaxf(sr[j + 1] + bb[j + 1], 0.f);
                float v2 = fmaxf(sr[j + 2] + bb[j + 2], 0.f);
                float v3 = fmaxf(sr[j + 3] + bb[j + 3], 0.f);
                *reinterpret_cast<float4*>(orow + j) = make_float4(v0, v1, v2, v3);
                if (write_split) {
                    __nv_bfloat16 h0, l0, h1, l1, h2, l2, h3, l3;
                    split_bf(v0, h0, l0); split_bf(v1, h1, l1);
                    split_bf(v2, h2, l2); split_bf(v3, h3, l3);
                    size_t so = (size_t)row * DH + half * 64 + j;
                    *reinterpret_cast<uint2*>(shi + so) = make_uint2(bfpack(h0, h1), bfpack(h2, h3));
                    *reinterpret_cast<uint2*>(slo + so) = make_uint2(bfpack(l0, l1), bfpack(l2, l3));
                }
            }
        }
    }
}

// ============ host ============
extern "C" void kernel_launch(void* const* d_in, const int* in_sizes, int n_in,
                              void* d_out, int out_size) {
    const float* x      = (const float*)d_in[0];
    const int*   ei     = (const int*)d_in[1];
    const float* ea     = (const float*)d_in[2];
    const float* Wrel[3]  = {(const float*)d_in[3], (const float*)d_in[6], (const float*)d_in[9]};
    const float* bv[3]    = {(const float*)d_in[4], (const float*)d_in[7], (const float*)d_in[10]};
    const float* Wroot[3] = {(const float*)d_in[5], (const float*)d_in[8], (const float*)d_in[11]};
    float* out = (float*)d_out;

    const int* src = ei;
    const int* dst = ei + NE;

    int *deg, *rowptr, *cursor, *csr_src;
    float *csr_w, *h1, *h2;
    __nv_bfloat16 *agghi, *agglo, *s0hi, *s0lo, *s1hi, *s1lo, *whi, *wlo;
    cudaGetSymbolAddress((void**)&deg,     g_deg);
    cudaGetSymbolAddress((void**)&rowptr,  g_rowptr);
    cudaGetSymbolAddress((void**)&cursor,  g_cursor);
    cudaGetSymbolAddress((void**)&csr_src, g_csr_src);
    cudaGetSymbolAddress((void**)&csr_w,   g_csr_w);
    cudaGetSymbolAddress((void**)&agghi,   g_agghi);
    cudaGetSymbolAddress((void**)&agglo,   g_agglo);
    cudaGetSymbolAddress((void**)&s0hi,    g_s0hi);
    cudaGetSymbolAddress((void**)&s0lo,    g_s0lo);
    cudaGetSymbolAddress((void**)&s1hi,    g_s1hi);
    cudaGetSymbolAddress((void**)&s1lo,    g_s1lo);
    cudaGetSymbolAddress((void**)&whi,     g_whi);
    cudaGetSymbolAddress((void**)&wlo,     g_wlo);
    cudaGetSymbolAddress((void**)&h1,      g_h1);
    cudaGetSymbolAddress((void**)&h2,      g_h2);

    cudaFuncSetAttribute(gemm_wmma_kernel,
                         cudaFuncAttributeMaxDynamicSharedMemorySize, GEMM_SMEM);

    // CSR build (once)
    cudaMemsetAsync(deg, 0, NN * sizeof(int));
    deg_count_kernel<<<(NE + 255) / 256, 256>>>(dst, deg);
    scan_kernel<<<1, 1024>>>(deg, rowptr, cursor);
    fill_csr_kernel<<<(NE + 255) / 256, 256>>>(src, dst, ea, cursor, csr_src, csr_w);

    // x split (layer-1 root input lives in s1) + weight prep
    split_x_kernel<<<(NN * DH + 255) / 256, 256>>>(x, s1hi, s1lo);
    for (int l = 0; l < 3; l++)
        prep_w_kernel<<<128, 256>>>(Wrel[l], Wroot[l], whi + l * 32768, wlo + l * 32768);

    // per-layer: gather -> wmma GEMM
    const float* cur = x;
    const __nv_bfloat16* sih[3] = {s1hi, s0hi, s1hi};
    const __nv_bfloat16* sil[3] = {s1lo, s0lo, s1lo};
    __nv_bfloat16* soh[3] = {s0hi, s1hi, nullptr};
    __nv_bfloat16* sol[3] = {s0lo, s1lo, nullptr};
    float* outs[3] = {h1, h2, out};
    int gather_blocks = (NN * 32 + 255) / 256;
    for (int l = 0; l < 3; l++) {
        gather_agg_kernel<<<gather_blocks, 256>>>(cur, rowptr, csr_src, csr_w, agghi, agglo);
        gemm_wmma_kernel<<<NTILES, 256, GEMM_SMEM>>>(
            agghi, agglo, sih[l], sil[l],
            whi + l * 32768, wlo + l * 32768, bv[l],
            outs[l], soh[l], sol[l], l < 2 ? 1 : 0);
        cur = outs[l];
    }
}

// round 6
// speedup vs baseline: 1.1903x; 1.1903x over previous
#include <cuda_runtime.h>
#include <cuda_bf16.h>
#include <mma.h>
#include <stdint.h>

using namespace nvcuda;

#define NN 100000
#define NE 1600000
#define DH 128
#define NTILES 782   // ceil(NN/128)

// ---- scratch (device globals; no allocation allowed) ----
__device__ int   g_deg[NN];
__device__ int   g_rowptr[NN + 1];
__device__ int   g_cursor[NN];
__device__ int   g_csr_src[NE];
__device__ float g_csr_w[NE];
__device__ float g_agg[NN * DH];
__device__ float g_h1[NN * DH];
__device__ float g_h2[NN * DH];
__device__ float g_tail[128 * DH];
__device__ __nv_bfloat16 g_whi[3 * 256 * 128];   // [layer][k][n] : k<128 Wrel, k>=128 Wroot
__device__ __nv_bfloat16 g_wlo[3 * 256 * 128];

// ============ small helpers ============
__device__ __forceinline__ uint32_t bfpack(__nv_bfloat16 a, __nv_bfloat16 b) {
    return (uint32_t)__bfloat16_as_ushort(a) | ((uint32_t)__bfloat16_as_ushort(b) << 16);
}
__device__ __forceinline__ void split_bf(float v, __nv_bfloat16& h, __nv_bfloat16& l) {
    h = __float2bfloat16_rn(v);
    l = __float2bfloat16_rn(v - __bfloat162float(h));
}

// ============ CSR build ============
__global__ void deg_count_kernel(const int* __restrict__ dst, int* __restrict__ deg) {
    int i = blockIdx.x * blockDim.x + threadIdx.x;
    if (i < NE) atomicAdd(&deg[dst[i]], 1);
}

__global__ void scan_kernel(const int* __restrict__ deg,
                            int* __restrict__ rowptr, int* __restrict__ cursor) {
    __shared__ int sdata[1024];
    __shared__ int carry;
    if (threadIdx.x == 0) carry = 0;
    __syncthreads();
    for (int base = 0; base < NN; base += 1024) {
        int i = base + (int)threadIdx.x;
        int v = (i < NN) ? deg[i] : 0;
        sdata[threadIdx.x] = v;
        __syncthreads();
        #pragma unroll
        for (int off = 1; off < 1024; off <<= 1) {
            int t = (threadIdx.x >= off) ? sdata[threadIdx.x - off] : 0;
            __syncthreads();
            sdata[threadIdx.x] += t;
            __syncthreads();
        }
        int excl = sdata[threadIdx.x] - v + carry;
        if (i < NN) { rowptr[i] = excl; cursor[i] = excl; }
        __syncthreads();
        if (threadIdx.x == 0) carry += sdata[1023];
        __syncthreads();
    }
    if (threadIdx.x == 0) rowptr[NN] = carry;
}

__global__ void fill_csr_kernel(const int* __restrict__ src, const int* __restrict__ dst,
                                const float* __restrict__ w, int* __restrict__ cursor,
                                int* __restrict__ csr_src, float* __restrict__ csr_w) {
    int e = blockIdx.x * blockDim.x + threadIdx.x;
    if (e < NE) {
        int d = dst[e];
        int p = atomicAdd(&cursor[d], 1);
        csr_src[p] = src[e];
        csr_w[p]   = w[e];
    }
}

// ============ weight prep: W[k][n], k<128 Wrel, k>=128 Wroot, bf16 hi/lo ============
__global__ void prep_w_kernel(const float* __restrict__ Wrel, const float* __restrict__ Wroot,
                              __nv_bfloat16* __restrict__ hi, __nv_bfloat16* __restrict__ lo) {
    int i = blockIdx.x * blockDim.x + threadIdx.x;
    if (i >= 256 * 128) return;
    int k = i >> 7;
    int n = i & 127;
    float v = (k < 128) ? Wrel[k * 128 + n] : Wroot[(k - 128) * 128 + n];
    __nv_bfloat16 h, l;
    split_bf(v, h, l);
    hi[i] = h; lo[i] = l;
}

// ============ aggregation: one warp per node, gather, mean fused, fp32 out ============
__global__ void gather_agg_kernel(const float* __restrict__ xin,
                                  const int* __restrict__ rowptr,
                                  const int* __restrict__ csr_src,
                                  const float* __restrict__ csr_w,
                                  float* __restrict__ agg) {
    unsigned gt = blockIdx.x * blockDim.x + threadIdx.x;
    unsigned node = gt >> 5;
    int lane = threadIdx.x & 31;
    if (node >= NN) return;
    int s0 = __ldg(rowptr + node);
    int s1 = __ldg(rowptr + node + 1);
    float4 acc = make_float4(0.f, 0.f, 0.f, 0.f);
    int e = s0;
    for (; e + 3 < s1; e += 4) {
        int   s_[4]; float w_[4];
        #pragma unroll
        for (int q = 0; q < 4; q++) { s_[q] = __ldg(csr_src + e + q); w_[q] = __ldg(csr_w + e + q); }
        float4 v_[4];
        #pragma unroll
        for (int q = 0; q < 4; q++)
            v_[q] = *reinterpret_cast<const float4*>(xin + (size_t)s_[q] * DH + lane * 4);
        #pragma unroll
        for (int q = 0; q < 4; q++) {
            acc.x = fmaf(w_[q], v_[q].x, acc.x); acc.y = fmaf(w_[q], v_[q].y, acc.y);
            acc.z = fmaf(w_[q], v_[q].z, acc.z); acc.w = fmaf(w_[q], v_[q].w, acc.w);
        }
    }
    for (; e < s1; e++) {
        int   sa = __ldg(csr_src + e);
        float wa = __ldg(csr_w + e);
        float4 va = *reinterpret_cast<const float4*>(xin + (size_t)sa * DH + lane * 4);
        acc.x = fmaf(wa, va.x, acc.x); acc.y = fmaf(wa, va.y, acc.y);
        acc.z = fmaf(wa, va.z, acc.z); acc.w = fmaf(wa, va.w, acc.w);
    }
    float di = (s1 > s0) ? 1.0f / (float)(s1 - s0) : 0.f;
    acc.x *= di; acc.y *= di; acc.z *= di; acc.w *= di;
    *reinterpret_cast<float4*>(agg + (size_t)node * DH + lane * 4) = acc;
}

// ============ persistent wmma GEMM: out = relu([agg|x]@[Wrel;Wroot] + b) ============
// 148 CTAs x 256 threads, loop over 128x128 tiles. B hi/lo resident in smem.
// A chunks (128x32) staged from fp32 with on-the-fly hi/lo split, double buffered.
// bias via rank-1 extra K-chunk MMA (exact, hi+lo rows); relu on fragments; direct global store.
#define BSTR 136
#define ASTR 40
#define OFF_BH 0u
#define OFF_BL 69632u
#define OFF_BB 139264u                       // bias B chunk: 16 x BSTR
#define OFF_AB 143616u                       // bias A chunk: 128 x ASTR (cols 0,1 = 1)
#define OFF_A  153856u                       // 4 x 10240
#define GEMM_SMEM (153856 + 4 * 10240)       // 194816

__global__ void __launch_bounds__(256, 1) gemm_persist_kernel(
    const float* __restrict__ agg, const float* __restrict__ xin,
    const __nv_bfloat16* __restrict__ whi, const __nv_bfloat16* __restrict__ wlo,
    const float* __restrict__ bias, float* __restrict__ hout, float* __restrict__ tail)
{
    extern __shared__ char smem[];
    __nv_bfloat16* BH = reinterpret_cast<__nv_bfloat16*>(smem + OFF_BH);
    __nv_bfloat16* BL = reinterpret_cast<__nv_bfloat16*>(smem + OFF_BL);
    __nv_bfloat16* BB = reinterpret_cast<__nv_bfloat16*>(smem + OFF_BB);
    __nv_bfloat16* AB = reinterpret_cast<__nv_bfloat16*>(smem + OFF_AB);
    __nv_bfloat16* AH[2] = {reinterpret_cast<__nv_bfloat16*>(smem + OFF_A),
                            reinterpret_cast<__nv_bfloat16*>(smem + OFF_A + 20480u)};
    __nv_bfloat16* AL[2] = {reinterpret_cast<__nv_bfloat16*>(smem + OFF_A + 10240u),
                            reinterpret_cast<__nv_bfloat16*>(smem + OFF_A + 30720u)};

    const int tid = threadIdx.x;
    const int wid = tid >> 5;
    const int wm = wid >> 1;      // 0..3 -> rows 32*wm
    const int wn = wid & 1;       // 0..1 -> cols 64*wn

    // one-time staging: B hi/lo, zero bias chunks
    #pragma unroll
    for (int j = 0; j < 16; j++) {
        int f = tid + j * 256;
        int r = f >> 4, c8 = f & 15;
        uint4 vh = *reinterpret_cast<const uint4*>(whi + (size_t)r * 128 + c8 * 8);
        uint4 vl = *reinterpret_cast<const uint4*>(wlo + (size_t)r * 128 + c8 * 8);
        *reinterpret_cast<uint4*>(BH + r * BSTR + c8 * 8) = vh;
        *reinterpret_cast<uint4*>(BL + r * BSTR + c8 * 8) = vl;
    }
    for (int i = tid; i < (16 * BSTR + 128 * ASTR) / 2; i += 256)
        reinterpret_cast<uint32_t*>(BB)[i] = 0;  // BB then AB contiguous
    __syncthreads();
    if (tid < 128) {
        __nv_bfloat16 h, l;
        split_bf(bias[tid], h, l);
        BB[0 * BSTR + tid] = h;
        BB[1 * BSTR + tid] = l;
        AB[tid * ASTR + 0] = __float2bfloat16_rn(1.0f);
        AB[tid * ASTR + 1] = __float2bfloat16_rn(1.0f);
    }
    __syncthreads();

    float4 rfa[2][4];  // staged fp32 A: [buffer-phase stub][4 float4]

    for (int tile = blockIdx.x; tile < NTILES; tile += 148) {
        const int row0 = tile * 128;
        const int r = tid >> 1;        // 0..127
        const int half = tid & 1;      // 16 floats each

        auto ldgA = [&](int c) {
            const float* p = (c < 4) ? agg : xin;
            const int k0 = (c & 3) * 32 + half * 16;
            int grow = row0 + r;
            if (grow < NN) {
                const float* pr = p + (size_t)grow * DH + k0;
                #pragma unroll
                for (int q = 0; q < 4; q++) rfa[0][q] = *reinterpret_cast<const float4*>(pr + q * 4);
            } else {
                #pragma unroll
                for (int q = 0; q < 4; q++) rfa[0][q] = make_float4(0.f, 0.f, 0.f, 0.f);
            }
        };
        auto stsA = [&](int b) {
            uint32_t hp[8], lp[8];
            #pragma unroll
            for (int q = 0; q < 4; q++) {
                __nv_bfloat16 h0, l0, h1, l1;
                split_bf(rfa[0][q].x, h0, l0); split_bf(rfa[0][q].y, h1, l1);
                hp[q * 2] = bfpack(h0, h1); lp[q * 2] = bfpack(l0, l1);
                split_bf(rfa[0][q].z, h0, l0); split_bf(rfa[0][q].w, h1, l1);
                hp[q * 2 + 1] = bfpack(h0, h1); lp[q * 2 + 1] = bfpack(l0, l1);
            }
            __nv_bfloat16* ph = AH[b] + r * ASTR + half * 16;
            __nv_bfloat16* pl = AL[b] + r * ASTR + half * 16;
            *reinterpret_cast<uint4*>(ph)     = *reinterpret_cast<uint4*>(hp);
            *reinterpret_cast<uint4*>(ph + 8) = *reinterpret_cast<uint4*>(hp + 4);
            *reinterpret_cast<uint4*>(pl)     = *reinterpret_cast<uint4*>(lp);
            *reinterpret_cast<uint4*>(pl + 8) = *reinterpret_cast<uint4*>(lp + 4);
        };

        wmma::fragment<wmma::accumulator, 16, 16, 16, float> acc[2][4];
        #pragma unroll
        for (int i = 0; i < 2; i++)
            #pragma unroll
            for (int j = 0; j < 4; j++) wmma::fill_fragment(acc[i][j], 0.f);

        // bias rank-1 chunk
        {
            wmma::fragment<wmma::matrix_a, 16, 16, 16, __nv_bfloat16, wmma::row_major> fa[2];
            wmma::fragment<wmma::matrix_b, 16, 16, 16, __nv_bfloat16, wmma::row_major> fb[4];
            #pragma unroll
            for (int i = 0; i < 2; i++)
                wmma::load_matrix_sync(fa[i], AB + (32 * wm + 16 * i) * ASTR, ASTR);
            #pragma unroll
            for (int j = 0; j < 4; j++)
                wmma::load_matrix_sync(fb[j], BB + 64 * wn + 16 * j, BSTR);
            #pragma unroll
            for (int i = 0; i < 2; i++)
                #pragma unroll
                for (int j = 0; j < 4; j++)
                    wmma::mma_sync(acc[i][j], fa[i], fb[j], acc[i][j]);
        }

        ldgA(0); stsA(0);
        __syncthreads();

        #pragma unroll 1
        for (int c = 0; c < 8; c++) {
            const int buf = c & 1;
            if (c < 7) ldgA(c + 1);
            #pragma unroll
            for (int kk = 0; kk < 2; kk++) {
                wmma::fragment<wmma::matrix_a, 16, 16, 16, __nv_bfloat16, wmma::row_major> fah[2], fal[2];
                wmma::fragment<wmma::matrix_b, 16, 16, 16, __nv_bfloat16, wmma::row_major> fbh[4], fbl[4];
                #pragma unroll
                for (int i = 0; i < 2; i++) {
                    wmma::load_matrix_sync(fah[i], AH[buf] + (32 * wm + 16 * i) * ASTR + kk * 16, ASTR);
                    wmma::load_matrix_sync(fal[i], AL[buf] + (32 * wm + 16 * i) * ASTR + kk * 16, ASTR);
                }
                const int krow = c * 32 + kk * 16;
                #pragma unroll
                for (int j = 0; j < 4; j++) {
                    wmma::load_matrix_sync(fbh[j], BH + krow * BSTR + 64 * wn + 16 * j, BSTR);
                    wmma::load_matrix_sync(fbl[j], BL + krow * BSTR + 64 * wn + 16 * j, BSTR);
                }
                #pragma unroll
                for (int i = 0; i < 2; i++)
                    #pragma unroll
                    for (int j = 0; j < 4; j++) {
                        wmma::mma_sync(acc[i][j], fah[i], fbh[j], acc[i][j]);
                        wmma::mma_sync(acc[i][j], fah[i], fbl[j], acc[i][j]);
                        wmma::mma_sync(acc[i][j], fal[i], fbh[j], acc[i][j]);
                    }
            }
            if (c < 7) {
                stsA(buf ^ 1);
                __syncthreads();
            }
        }

        // relu on fragments, then store
        #pragma unroll
        for (int i = 0; i < 2; i++)
            #pragma unroll
            for (int j = 0; j < 4; j++)
                #pragma unroll
                for (int e = 0; e < acc[i][j].num_elements; e++)
                    acc[i][j].x[e] = fmaxf(acc[i][j].x[e], 0.f);

        if (row0 + 128 <= NN) {
            #pragma unroll
            for (int i = 0; i < 2; i++)
                #pragma unroll
                for (int j = 0; j < 4; j++)
                    wmma::store_matrix_sync(hout + (size_t)(row0 + 32 * wm + 16 * i) * DH + 64 * wn + 16 * j,
                                            acc[i][j], DH, wmma::mem_row_major);
        } else {
            #pragma unroll
            for (int i = 0; i < 2; i++)
                #pragma unroll
                for (int j = 0; j < 4; j++)
                    wmma::store_matrix_sync(tail + (size_t)(32 * wm + 16 * i) * DH + 64 * wn + 16 * j,
                                            acc[i][j], DH, wmma::mem_row_major);
            __syncthreads();
            int grow = row0 + r;
            if (grow < NN) {
                const float* srow = tail + (size_t)r * DH + half * 64;
                float* drow = hout + (size_t)grow * DH + half * 64;
                #pragma unroll
                for (int q = 0; q < 16; q++)
                    *reinterpret_cast<float4*>(drow + q * 4) =
                        *reinterpret_cast<const float4*>(srow + q * 4);
            }
        }
        __syncthreads();  // A buffers reusable next tile
    }
}

// ============ host ============
extern "C" void kernel_launch(void* const* d_in, const int* in_sizes, int n_in,
                              void* d_out, int out_size) {
    const float* x      = (const float*)d_in[0];
    const int*   ei     = (const int*)d_in[1];
    const float* ea     = (const float*)d_in[2];
    const float* Wrel[3]  = {(const float*)d_in[3], (const float*)d_in[6], (const float*)d_in[9]};
    const float* bv[3]    = {(const float*)d_in[4], (const float*)d_in[7], (const float*)d_in[10]};
    const float* Wroot[3] = {(const float*)d_in[5], (const float*)d_in[8], (const float*)d_in[11]};
    float* out = (float*)d_out;

    const int* src = ei;
    const int* dst = ei + NE;

    int *deg, *rowptr, *cursor, *csr_src;
    float *csr_w, *agg, *h1, *h2, *tail;
    __nv_bfloat16 *whi, *wlo;
    cudaGetSymbolAddress((void**)&deg,     g_deg);
    cudaGetSymbolAddress((void**)&rowptr,  g_rowptr);
    cudaGetSymbolAddress((void**)&cursor,  g_cursor);
    cudaGetSymbolAddress((void**)&csr_src, g_csr_src);
    cudaGetSymbolAddress((void**)&csr_w,   g_csr_w);
    cudaGetSymbolAddress((void**)&agg,     g_agg);
    cudaGetSymbolAddress((void**)&h1,      g_h1);
    cudaGetSymbolAddress((void**)&h2,      g_h2);
    cudaGetSymbolAddress((void**)&tail,    g_tail);
    cudaGetSymbolAddress((void**)&whi,     g_whi);
    cudaGetSymbolAddress((void**)&wlo,     g_wlo);

    cudaFuncSetAttribute(gemm_persist_kernel,
                         cudaFuncAttributeMaxDynamicSharedMemorySize, GEMM_SMEM);

    // CSR build (once)
    cudaMemsetAsync(deg, 0, NN * sizeof(int));
    deg_count_kernel<<<(NE + 255) / 256, 256>>>(dst, deg);
    scan_kernel<<<1, 1024>>>(deg, rowptr, cursor);
    fill_csr_kernel<<<(NE + 255) / 256, 256>>>(src, dst, ea, cursor, csr_src, csr_w);

    for (int l = 0; l < 3; l++)
        prep_w_kernel<<<128, 256>>>(Wrel[l], Wroot[l], whi + l * 32768, wlo + l * 32768);

    const float* cur = x;
    float* outs[3] = {h1, h2, out};
    int gather_blocks = (NN * 32 + 255) / 256;
    for (int l = 0; l < 3; l++) {
        gather_agg_kernel<<<gather_blocks, 256>>>(cur, rowptr, csr_src, csr_w, agg);
        gemm_persist_kernel<<<148, 256, GEMM_SMEM>>>(
            agg, cur, whi + l * 32768, wlo + l * 32768, bv[l], outs[l], tail);
        cur = outs[l];
    }
}

// round 7
// speedup vs baseline: 1.3480x; 1.1324x over previous
#include <cuda_runtime.h>
#include <cuda_bf16.h>
#include <mma.h>
#include <stdint.h>

using namespace nvcuda;

#define NN 100000
#define NE 1600000
#define DH 128
#define NTILES 782   // ceil(NN/128)

// ---- scratch (device globals; no allocation allowed) ----
__device__ int   g_deg[NN];
__device__ int   g_rowptr[NN + 1];
__device__ int   g_cursor[NN];
__device__ int   g_csr_src[NE];
__device__ float g_csr_w[NE];
__device__ float g_agg[NN * DH];
__device__ float g_h1[NN * DH];
__device__ float g_h2[NN * DH];
__device__ float g_tail[128 * DH];
__device__ __nv_bfloat16 g_whi[3 * 256 * 128];   // [layer][k][n] : k<128 Wrel, k>=128 Wroot
__device__ __nv_bfloat16 g_wlo[3 * 256 * 128];

// ============ small helpers ============
__device__ __forceinline__ uint32_t bfpack(__nv_bfloat16 a, __nv_bfloat16 b) {
    return (uint32_t)__bfloat16_as_ushort(a) | ((uint32_t)__bfloat16_as_ushort(b) << 16);
}
__device__ __forceinline__ void split_bf(float v, __nv_bfloat16& h, __nv_bfloat16& l) {
    h = __float2bfloat16_rn(v);
    l = __float2bfloat16_rn(v - __bfloat162float(h));
}

// ============ CSR build ============
__global__ void deg_count_kernel(const int* __restrict__ dst, int* __restrict__ deg) {
    int i = blockIdx.x * blockDim.x + threadIdx.x;
    if (i < NE) atomicAdd(&deg[dst[i]], 1);
}

// single-block exclusive scan, shuffle-based
__global__ void scan_kernel(const int* __restrict__ deg,
                            int* __restrict__ rowptr, int* __restrict__ cursor) {
    __shared__ int wsum[32];
    __shared__ int carry;
    const int tid = threadIdx.x, lane = tid & 31, warp = tid >> 5;
    if (tid == 0) carry = 0;
    __syncthreads();
    for (int base = 0; base < NN; base += 1024) {
        int i = base + tid;
        int v = (i < NN) ? deg[i] : 0;
        int s = v;
        #pragma unroll
        for (int off = 1; off < 32; off <<= 1) {
            int t = __shfl_up_sync(0xFFFFFFFF, s, off);
            if (lane >= off) s += t;
        }
        if (lane == 31) wsum[warp] = s;
        __syncthreads();
        if (warp == 0) {
            int w = wsum[lane];
            #pragma unroll
            for (int off = 1; off < 32; off <<= 1) {
                int t = __shfl_up_sync(0xFFFFFFFF, w, off);
                if (lane >= off) w += t;
            }
            wsum[lane] = w;
        }
        __syncthreads();
        int excl = s - v + (warp > 0 ? wsum[warp - 1] : 0) + carry;
        if (i < NN) { rowptr[i] = excl; cursor[i] = excl; }
        __syncthreads();
        if (tid == 0) carry += wsum[31];
        __syncthreads();
    }
    if (threadIdx.x == 0) rowptr[NN] = carry;
}

__global__ void fill_csr_kernel(const int* __restrict__ src, const int* __restrict__ dst,
                                const float* __restrict__ w, int* __restrict__ cursor,
                                int* __restrict__ csr_src, float* __restrict__ csr_w) {
    int e = blockIdx.x * blockDim.x + threadIdx.x;
    if (e < NE) {
        int d = dst[e];
        int p = atomicAdd(&cursor[d], 1);
        csr_src[p] = src[e];
        csr_w[p]   = w[e];
    }
}

// ============ weight prep: W[k][n], k<128 Wrel, k>=128 Wroot, bf16 hi/lo ============
__global__ void prep_w_kernel(const float* __restrict__ Wrel, const float* __restrict__ Wroot,
                              __nv_bfloat16* __restrict__ hi, __nv_bfloat16* __restrict__ lo) {
    int i = blockIdx.x * blockDim.x + threadIdx.x;
    if (i >= 256 * 128) return;
    int k = i >> 7;
    int n = i & 127;
    float v = (k < 128) ? Wrel[k * 128 + n] : Wroot[(k - 128) * 128 + n];
    __nv_bfloat16 h, l;
    split_bf(v, h, l);
    hi[i] = h; lo[i] = l;
}

// ============ aggregation: one warp per node, gather, mean fused, fp32 out ============
__global__ void gather_agg_kernel(const float* __restrict__ xin,
                                  const int* __restrict__ rowptr,
                                  const int* __restrict__ csr_src,
                                  const float* __restrict__ csr_w,
                                  float* __restrict__ agg) {
    unsigned gt = blockIdx.x * blockDim.x + threadIdx.x;
    unsigned node = gt >> 5;
    int lane = threadIdx.x & 31;
    if (node >= NN) return;
    int s0 = __ldg(rowptr + node);
    int s1 = __ldg(rowptr + node + 1);
    float4 acc = make_float4(0.f, 0.f, 0.f, 0.f);
    int e = s0;
    for (; e + 3 < s1; e += 4) {
        int   s_[4]; float w_[4];
        #pragma unroll
        for (int q = 0; q < 4; q++) { s_[q] = __ldg(csr_src + e + q); w_[q] = __ldg(csr_w + e + q); }
        float4 v_[4];
        #pragma unroll
        for (int q = 0; q < 4; q++)
            v_[q] = *reinterpret_cast<const float4*>(xin + (size_t)s_[q] * DH + lane * 4);
        #pragma unroll
        for (int q = 0; q < 4; q++) {
            acc.x = fmaf(w_[q], v_[q].x, acc.x); acc.y = fmaf(w_[q], v_[q].y, acc.y);
            acc.z = fmaf(w_[q], v_[q].z, acc.z); acc.w = fmaf(w_[q], v_[q].w, acc.w);
        }
    }
    for (; e < s1; e++) {
        int   sa = __ldg(csr_src + e);
        float wa = __ldg(csr_w + e);
        float4 va = *reinterpret_cast<const float4*>(xin + (size_t)sa * DH + lane * 4);
        acc.x = fmaf(wa, va.x, acc.x); acc.y = fmaf(wa, va.y, acc.y);
        acc.z = fmaf(wa, va.z, acc.z); acc.w = fmaf(wa, va.w, acc.w);
    }
    float di = (s1 > s0) ? 1.0f / (float)(s1 - s0) : 0.f;
    acc.x *= di; acc.y *= di; acc.z *= di; acc.w *= di;
    *reinterpret_cast<float4*>(agg + (size_t)node * DH + lane * 4) = acc;
}

// ============ persistent wmma GEMM: out = relu([agg|x]@[Wrel;Wroot] + b) ============
// 148 CTAs x 512 threads (16 warps, 4x4 grid, 32x32 warp tiles). B hi/lo smem-resident.
// A chunks (128x32) staged from fp32 with in-register hi/lo split, double buffered.
#define BSTR 136
#define ASTR 40
#define OFF_BH 0u
#define OFF_BL 69632u
#define OFF_BB 139264u                       // bias B chunk: 16 x BSTR
#define OFF_AB 143616u                       // bias A chunk: 128 x ASTR (cols 0,1 = 1)
#define OFF_A  153856u                       // 4 x 10240
#define GEMM_SMEM (153856 + 4 * 10240)       // 194816

__global__ void __launch_bounds__(512, 1) gemm_persist_kernel(
    const float* __restrict__ agg, const float* __restrict__ xin,
    const __nv_bfloat16* __restrict__ whi, const __nv_bfloat16* __restrict__ wlo,
    const float* __restrict__ bias, float* __restrict__ hout, float* __restrict__ tail)
{
    extern __shared__ char smem[];
    __nv_bfloat16* BH = reinterpret_cast<__nv_bfloat16*>(smem + OFF_BH);
    __nv_bfloat16* BL = reinterpret_cast<__nv_bfloat16*>(smem + OFF_BL);
    __nv_bfloat16* BB = reinterpret_cast<__nv_bfloat16*>(smem + OFF_BB);
    __nv_bfloat16* AB = reinterpret_cast<__nv_bfloat16*>(smem + OFF_AB);
    __nv_bfloat16* AH[2] = {reinterpret_cast<__nv_bfloat16*>(smem + OFF_A),
                            reinterpret_cast<__nv_bfloat16*>(smem + OFF_A + 20480u)};
    __nv_bfloat16* AL[2] = {reinterpret_cast<__nv_bfloat16*>(smem + OFF_A + 10240u),
                            reinterpret_cast<__nv_bfloat16*>(smem + OFF_A + 30720u)};

    const int tid = threadIdx.x;
    const int wid = tid >> 5;
    const int wm = wid >> 2;      // 0..3 -> rows 32*wm
    const int wn = wid & 3;       // 0..3 -> cols 32*wn

    // one-time staging: B hi/lo (512 threads), zero + fill bias chunks
    #pragma unroll
    for (int j = 0; j < 8; j++) {
        int f = tid + j * 512;
        int r = f >> 4, c8 = f & 15;
        uint4 vh = *reinterpret_cast<const uint4*>(whi + (size_t)r * 128 + c8 * 8);
        uint4 vl = *reinterpret_cast<const uint4*>(wlo + (size_t)r * 128 + c8 * 8);
        *reinterpret_cast<uint4*>(BH + r * BSTR + c8 * 8) = vh;
        *reinterpret_cast<uint4*>(BL + r * BSTR + c8 * 8) = vl;
    }
    for (int i = tid; i < (16 * BSTR + 128 * ASTR) / 2; i += 512)
        reinterpret_cast<uint32_t*>(BB)[i] = 0;  // BB then AB contiguous
    __syncthreads();
    if (tid < 128) {
        __nv_bfloat16 h, l;
        split_bf(bias[tid], h, l);
        BB[0 * BSTR + tid] = h;
        BB[1 * BSTR + tid] = l;
        AB[tid * ASTR + 0] = __float2bfloat16_rn(1.0f);
        AB[tid * ASTR + 1] = __float2bfloat16_rn(1.0f);
    }
    __syncthreads();

    float4 rfa[2];  // staged fp32 A: 8 floats per thread

    for (int tile = blockIdx.x; tile < NTILES; tile += 148) {
        const int row0 = tile * 128;
        const int r = tid >> 2;        // 0..127
        const int quarter = tid & 3;   // 8 floats each

        auto ldgA = [&](int c) {
            const float* p = (c < 4) ? agg : xin;
            const int k0 = (c & 3) * 32 + quarter * 8;
            int grow = row0 + r;
            if (grow < NN) {
                const float* pr = p + (size_t)grow * DH + k0;
                rfa[0] = *reinterpret_cast<const float4*>(pr);
                rfa[1] = *reinterpret_cast<const float4*>(pr + 4);
            } else {
                rfa[0] = make_float4(0.f, 0.f, 0.f, 0.f);
                rfa[1] = make_float4(0.f, 0.f, 0.f, 0.f);
            }
        };
        auto stsA = [&](int b) {
            uint32_t hp[4], lp[4];
            #pragma unroll
            for (int q = 0; q < 2; q++) {
                __nv_bfloat16 h0, l0, h1, l1;
                split_bf(rfa[q].x, h0, l0); split_bf(rfa[q].y, h1, l1);
                hp[q * 2] = bfpack(h0, h1); lp[q * 2] = bfpack(l0, l1);
                split_bf(rfa[q].z, h0, l0); split_bf(rfa[q].w, h1, l1);
                hp[q * 2 + 1] = bfpack(h0, h1); lp[q * 2 + 1] = bfpack(l0, l1);
            }
            *reinterpret_cast<uint4*>(AH[b] + r * ASTR + quarter * 8) = *reinterpret_cast<uint4*>(hp);
            *reinterpret_cast<uint4*>(AL[b] + r * ASTR + quarter * 8) = *reinterpret_cast<uint4*>(lp);
        };

        wmma::fragment<wmma::accumulator, 16, 16, 16, float> acc[2][2];
        #pragma unroll
        for (int i = 0; i < 2; i++)
            #pragma unroll
            for (int j = 0; j < 2; j++) wmma::fill_fragment(acc[i][j], 0.f);

        // bias rank-1 chunk
        {
            wmma::fragment<wmma::matrix_a, 16, 16, 16, __nv_bfloat16, wmma::row_major> fa[2];
            wmma::fragment<wmma::matrix_b, 16, 16, 16, __nv_bfloat16, wmma::row_major> fb[2];
            #pragma unroll
            for (int i = 0; i < 2; i++)
                wmma::load_matrix_sync(fa[i], AB + (32 * wm + 16 * i) * ASTR, ASTR);
            #pragma unroll
            for (int j = 0; j < 2; j++)
                wmma::load_matrix_sync(fb[j], BB + 32 * wn + 16 * j, BSTR);
            #pragma unroll
            for (int i = 0; i < 2; i++)
                #pragma unroll
                for (int j = 0; j < 2; j++)
                    wmma::mma_sync(acc[i][j], fa[i], fb[j], acc[i][j]);
        }

        ldgA(0); stsA(0);
        __syncthreads();

        #pragma unroll 1
        for (int c = 0; c < 8; c++) {
            const int buf = c & 1;
            if (c < 7) ldgA(c + 1);
            #pragma unroll
            for (int kk = 0; kk < 2; kk++) {
                wmma::fragment<wmma::matrix_a, 16, 16, 16, __nv_bfloat16, wmma::row_major> fah[2], fal[2];
                wmma::fragment<wmma::matrix_b, 16, 16, 16, __nv_bfloat16, wmma::row_major> fbh[2], fbl[2];
                #pragma unroll
                for (int i = 0; i < 2; i++) {
                    wmma::load_matrix_sync(fah[i], AH[buf] + (32 * wm + 16 * i) * ASTR + kk * 16, ASTR);
                    wmma::load_matrix_sync(fal[i], AL[buf] + (32 * wm + 16 * i) * ASTR + kk * 16, ASTR);
                }
                const int krow = c * 32 + kk * 16;
                #pragma unroll
                for (int j = 0; j < 2; j++) {
                    wmma::load_matrix_sync(fbh[j], BH + krow * BSTR + 32 * wn + 16 * j, BSTR);
                    wmma::load_matrix_sync(fbl[j], BL + krow * BSTR + 32 * wn + 16 * j, BSTR);
                }
                #pragma unroll
                for (int i = 0; i < 2; i++)
                    #pragma unroll
                    for (int j = 0; j < 2; j++) {
                        wmma::mma_sync(acc[i][j], fah[i], fbh[j], acc[i][j]);
                        wmma::mma_sync(acc[i][j], fah[i], fbl[j], acc[i][j]);
                        wmma::mma_sync(acc[i][j], fal[i], fbh[j], acc[i][j]);
                    }
            }
            if (c < 7) {
                stsA(buf ^ 1);
                __syncthreads();
            }
        }

        // relu on fragments, then store
        #pragma unroll
        for (int i = 0; i < 2; i++)
            #pragma unroll
            for (int j = 0; j < 2; j++)
                #pragma unroll
                for (int e = 0; e < acc[i][j].num_elements; e++)
                    acc[i][j].x[e] = fmaxf(acc[i][j].x[e], 0.f);

        if (row0 + 128 <= NN) {
            #pragma unroll
            for (int i = 0; i < 2; i++)
                #pragma unroll
                for (int j = 0; j < 2; j++)
                    wmma::store_matrix_sync(hout + (size_t)(row0 + 32 * wm + 16 * i) * DH + 32 * wn + 16 * j,
                                            acc[i][j], DH, wmma::mem_row_major);
        } else {
            #pragma unroll
            for (int i = 0; i < 2; i++)
                #pragma unroll
                for (int j = 0; j < 2; j++)
                    wmma::store_matrix_sync(tail + (size_t)(32 * wm + 16 * i) * DH + 32 * wn + 16 * j,
                                            acc[i][j], DH, wmma::mem_row_major);
            __syncthreads();
            int grow = row0 + r;
            if (grow < NN) {
                const float* srow = tail + (size_t)r * DH + quarter * 32;
                float* drow = hout + (size_t)grow * DH + quarter * 32;
                #pragma unroll
                for (int q = 0; q < 8; q++)
                    *reinterpret_cast<float4*>(drow + q * 4) =
                        *reinterpret_cast<const float4*>(srow + q * 4);
            }
        }
        __syncthreads();  // A buffers reusable next tile
    }
}

// ============ host ============
extern "C" void kernel_launch(void* const* d_in, const int* in_sizes, int n_in,
                              void* d_out, int out_size) {
    const float* x      = (const float*)d_in[0];
    const int*   ei     = (const int*)d_in[1];
    const float* ea     = (const float*)d_in[2];
    const float* Wrel[3]  = {(const float*)d_in[3], (const float*)d_in[6], (const float*)d_in[9]};
    const float* bv[3]    = {(const float*)d_in[4], (const float*)d_in[7], (const float*)d_in[10]};
    const float* Wroot[3] = {(const float*)d_in[5], (const float*)d_in[8], (const float*)d_in[11]};
    float* out = (float*)d_out;

    const int* src = ei;
    const int* dst = ei + NE;

    int *deg, *rowptr, *cursor, *csr_src;
    float *csr_w, *agg, *h1, *h2, *tail;
    __nv_bfloat16 *whi, *wlo;
    cudaGetSymbolAddress((void**)&deg,     g_deg);
    cudaGetSymbolAddress((void**)&rowptr,  g_rowptr);
    cudaGetSymbolAddress((void**)&cursor,  g_cursor);
    cudaGetSymbolAddress((void**)&csr_src, g_csr_src);
    cudaGetSymbolAddress((void**)&csr_w,   g_csr_w);
    cudaGetSymbolAddress((void**)&agg,     g_agg);
    cudaGetSymbolAddress((void**)&h1,      g_h1);
    cudaGetSymbolAddress((void**)&h2,      g_h2);
    cudaGetSymbolAddress((void**)&tail,    g_tail);
    cudaGetSymbolAddress((void**)&whi,     g_whi);
    cudaGetSymbolAddress((void**)&wlo,     g_wlo);

    cudaFuncSetAttribute(gemm_persist_kernel,
                         cudaFuncAttributeMaxDynamicSharedMemorySize, GEMM_SMEM);

    // CSR build (once)
    cudaMemsetAsync(deg, 0, NN * sizeof(int));
    deg_count_kernel<<<(NE + 255) / 256, 256>>>(dst, deg);
    scan_kernel<<<1, 1024>>>(deg, rowptr, cursor);
    fill_csr_kernel<<<(NE + 255) / 256, 256>>>(src, dst, ea, cursor, csr_src, csr_w);

    for (int l = 0; l < 3; l++)
        prep_w_kernel<<<128, 256>>>(Wrel[l], Wroot[l], whi + l * 32768, wlo + l * 32768);

    const float* cur = x;
    float* outs[3] = {h1, h2, out};
    int gather_blocks = (NN * 32 + 255) / 256;
    for (int l = 0; l < 3; l++) {
        gather_agg_kernel<<<gather_blocks, 256>>>(cur, rowptr, csr_src, csr_w, agg);
        gemm_persist_kernel<<<148, 512, GEMM_SMEM>>>(
            agg, cur, whi + l * 32768, wlo + l * 32768, bv[l], outs[l], tail);
        cur = outs[l];
    }
}

// round 8
// speedup vs baseline: 1.3948x; 1.0347x over previous
#include <cuda_runtime.h>
#include <cuda_bf16.h>
#include <mma.h>
#include <stdint.h>

using namespace nvcuda;

#define NN 100000
#define NE 1600000
#define DH 128
#define NTILES 782   // ceil(NN/128)

// ---- scratch (device globals; no allocation allowed) ----
__device__ int   g_deg[NN];
__device__ int   g_rowptr[NN + 1];
__device__ int   g_cursor[NN];
__device__ uint2 g_csr[NE];                      // (src, w-bits) packed
__device__ __nv_bfloat16 g_agghi[NN * DH];
__device__ __nv_bfloat16 g_agglo[NN * DH];
__device__ __nv_bfloat16 g_xhi[NN * DH];
__device__ __nv_bfloat16 g_xlo[NN * DH];
__device__ __nv_bfloat16 g_h1hi[NN * DH];
__device__ __nv_bfloat16 g_h1lo[NN * DH];
__device__ __nv_bfloat16 g_h2hi[NN * DH];
__device__ __nv_bfloat16 g_h2lo[NN * DH];
__device__ float g_tail[128 * DH];
__device__ __nv_bfloat16 g_whi[3 * 256 * 128];   // [layer][k][n] : k<128 Wrel, k>=128 Wroot
__device__ __nv_bfloat16 g_wlo[3 * 256 * 128];

// ============ small helpers ============
__device__ __forceinline__ uint32_t bfpack(__nv_bfloat16 a, __nv_bfloat16 b) {
    return (uint32_t)__bfloat16_as_ushort(a) | ((uint32_t)__bfloat16_as_ushort(b) << 16);
}
__device__ __forceinline__ void split_bf(float v, __nv_bfloat16& h, __nv_bfloat16& l) {
    h = __float2bfloat16_rn(v);
    l = __float2bfloat16_rn(v - __bfloat162float(h));
}
__device__ __forceinline__ float2 bf2f2(uint32_t u) {
    __nv_bfloat162 b = *reinterpret_cast<__nv_bfloat162*>(&u);
    return __bfloat1622float2(b);
}

// ============ CSR build ============
__global__ void deg_count_kernel(const int* __restrict__ dst, int* __restrict__ deg) {
    int i = blockIdx.x * blockDim.x + threadIdx.x;
    if (i < NE) atomicAdd(&deg[dst[i]], 1);
}

__global__ void scan_kernel(const int* __restrict__ deg,
                            int* __restrict__ rowptr, int* __restrict__ cursor) {
    __shared__ int wsum[32];
    __shared__ int carry;
    const int tid = threadIdx.x, lane = tid & 31, warp = tid >> 5;
    if (tid == 0) carry = 0;
    __syncthreads();
    for (int base = 0; base < NN; base += 1024) {
        int i = base + tid;
        int v = (i < NN) ? deg[i] : 0;
        int s = v;
        #pragma unroll
        for (int off = 1; off < 32; off <<= 1) {
            int t = __shfl_up_sync(0xFFFFFFFF, s, off);
            if (lane >= off) s += t;
        }
        if (lane == 31) wsum[warp] = s;
        __syncthreads();
        if (warp == 0) {
            int w = wsum[lane];
            #pragma unroll
            for (int off = 1; off < 32; off <<= 1) {
                int t = __shfl_up_sync(0xFFFFFFFF, w, off);
                if (lane >= off) w += t;
            }
            wsum[lane] = w;
        }
        __syncthreads();
        int excl = s - v + (warp > 0 ? wsum[warp - 1] : 0) + carry;
        if (i < NN) { rowptr[i] = excl; cursor[i] = excl; }
        __syncthreads();
        if (tid == 0) carry += wsum[31];
        __syncthreads();
    }
    if (threadIdx.x == 0) rowptr[NN] = carry;
}

__global__ void fill_csr_kernel(const int* __restrict__ src, const int* __restrict__ dst,
                                const float* __restrict__ w, int* __restrict__ cursor,
                                uint2* __restrict__ csr) {
    int e = blockIdx.x * blockDim.x + threadIdx.x;
    if (e < NE) {
        int d = dst[e];
        int p = atomicAdd(&cursor[d], 1);
        csr[p] = make_uint2((unsigned)src[e], __float_as_uint(w[e]));
    }
}

// ============ x split (once) ============
__global__ void split_x_kernel(const float* __restrict__ x,
                               __nv_bfloat16* __restrict__ hi, __nv_bfloat16* __restrict__ lo) {
    int i = blockIdx.x * blockDim.x + threadIdx.x;   // per 4 elems
    if (i >= NN * DH / 4) return;
    float4 v = *reinterpret_cast<const float4*>(x + (size_t)i * 4);
    __nv_bfloat16 h0, l0, h1, l1, h2, l2, h3, l3;
    split_bf(v.x, h0, l0); split_bf(v.y, h1, l1);
    split_bf(v.z, h2, l2); split_bf(v.w, h3, l3);
    *reinterpret_cast<uint2*>(hi + (size_t)i * 4) = make_uint2(bfpack(h0, h1), bfpack(h2, h3));
    *reinterpret_cast<uint2*>(lo + (size_t)i * 4) = make_uint2(bfpack(l0, l1), bfpack(l2, l3));
}

// ============ weight prep, all 3 layers in one launch ============
__global__ void prep_w_kernel(const float* __restrict__ Wrel1, const float* __restrict__ Wroot1,
                              const float* __restrict__ Wrel2, const float* __restrict__ Wroot2,
                              const float* __restrict__ Wrel3, const float* __restrict__ Wroot3,
                              __nv_bfloat16* __restrict__ hi, __nv_bfloat16* __restrict__ lo) {
    int i = blockIdx.x * blockDim.x + threadIdx.x;
    if (i >= 3 * 256 * 128) return;
    int l = i >> 15;
    int j = i & 32767;
    int k = j >> 7, n = j & 127;
    const float* Wrel  = (l == 0) ? Wrel1  : (l == 1) ? Wrel2  : Wrel3;
    const float* Wroot = (l == 0) ? Wroot1 : (l == 1) ? Wroot2 : Wroot3;
    float v = (k < 128) ? Wrel[k * 128 + n] : Wroot[(k - 128) * 128 + n];
    __nv_bfloat16 h, lw;
    split_bf(v, h, lw);
    hi[i] = h; lo[i] = lw;
}

// ============ aggregation: one warp per node; reads hi/lo planes; writes hi/lo ============
__global__ void gather_agg_kernel(const __nv_bfloat16* __restrict__ inhi,
                                  const __nv_bfloat16* __restrict__ inlo,
                                  const int* __restrict__ rowptr,
                                  const uint2* __restrict__ csr,
                                  __nv_bfloat16* __restrict__ agghi,
                                  __nv_bfloat16* __restrict__ agglo) {
    unsigned gt = blockIdx.x * blockDim.x + threadIdx.x;
    unsigned node = gt >> 5;
    int lane = threadIdx.x & 31;
    if (node >= NN) return;
    int s0 = __ldg(rowptr + node);
    int s1 = __ldg(rowptr + node + 1);
    float4 acc = make_float4(0.f, 0.f, 0.f, 0.f);
    int e = s0;
    for (; e + 1 < s1; e += 2) {
        uint2 e0 = __ldg(csr + e);
        uint2 e1 = __ldg(csr + e + 1);
        size_t o0 = (size_t)e0.x * DH + lane * 4;
        size_t o1 = (size_t)e1.x * DH + lane * 4;
        uint2 h0 = *reinterpret_cast<const uint2*>(inhi + o0);
        uint2 l0 = *reinterpret_cast<const uint2*>(inlo + o0);
        uint2 h1 = *reinterpret_cast<const uint2*>(inhi + o1);
        uint2 l1 = *reinterpret_cast<const uint2*>(inlo + o1);
        float w0 = __uint_as_float(e0.y), w1 = __uint_as_float(e1.y);
        float2 a, b;
        a = bf2f2(h0.x); b = bf2f2(l0.x);
        acc.x = fmaf(w0, a.x + b.x, acc.x); acc.y = fmaf(w0, a.y + b.y, acc.y);
        a = bf2f2(h0.y); b = bf2f2(l0.y);
        acc.z = fmaf(w0, a.x + b.x, acc.z); acc.w = fmaf(w0, a.y + b.y, acc.w);
        a = bf2f2(h1.x); b = bf2f2(l1.x);
        acc.x = fmaf(w1, a.x + b.x, acc.x); acc.y = fmaf(w1, a.y + b.y, acc.y);
        a = bf2f2(h1.y); b = bf2f2(l1.y);
        acc.z = fmaf(w1, a.x + b.x, acc.z); acc.w = fmaf(w1, a.y + b.y, acc.w);
    }
    if (e < s1) {
        uint2 e0 = __ldg(csr + e);
        size_t o0 = (size_t)e0.x * DH + lane * 4;
        uint2 h0 = *reinterpret_cast<const uint2*>(inhi + o0);
        uint2 l0 = *reinterpret_cast<const uint2*>(inlo + o0);
        float w0 = __uint_as_float(e0.y);
        float2 a, b;
        a = bf2f2(h0.x); b = bf2f2(l0.x);
        acc.x = fmaf(w0, a.x + b.x, acc.x); acc.y = fmaf(w0, a.y + b.y, acc.y);
        a = bf2f2(h0.y); b = bf2f2(l0.y);
        acc.z = fmaf(w0, a.x + b.x, acc.z); acc.w = fmaf(w0, a.y + b.y, acc.w);
    }
    float di = (s1 > s0) ? 1.0f / (float)(s1 - s0) : 0.f;
    acc.x *= di; acc.y *= di; acc.z *= di; acc.w *= di;

    __nv_bfloat16 h0, l0, h1, l1, h2, l2, h3, l3;
    split_bf(acc.x, h0, l0); split_bf(acc.y, h1, l1);
    split_bf(acc.z, h2, l2); split_bf(acc.w, h3, l3);
    size_t off = (size_t)node * DH + lane * 4;
    *reinterpret_cast<uint2*>(agghi + off) = make_uint2(bfpack(h0, h1), bfpack(h2, h3));
    *reinterpret_cast<uint2*>(agglo + off) = make_uint2(bfpack(l0, l1), bfpack(l2, l3));
}

// ============ persistent wmma GEMM: relu([agg|x]@[Wrel;Wroot] + b) ============
// 148 CTAs x 512 threads (16 warps, 4x4, 32x32 warp tiles). B hi/lo smem-resident.
// A chunks staged by cp.async (bf16 hi/lo direct), 3-stage ring, 1 barrier/chunk.
#define BSTR 136
#define ASTR 40
#define OFF_BH 0u
#define OFF_BL 69632u
#define OFF_BB 139264u                       // bias B chunk: 16 x BSTR
#define OFF_AB 143616u                       // bias A chunk: 128 x ASTR (cols 0,1 = 1)
#define OFF_A  153856u                       // 3 stages x (AH 10240 + AL 10240)
#define GEMM_SMEM (153856 + 3 * 20480)       // 215296

__global__ void __launch_bounds__(512, 1) gemm_persist_kernel(
    const __nv_bfloat16* __restrict__ agghi, const __nv_bfloat16* __restrict__ agglo,
    const __nv_bfloat16* __restrict__ xhi,   const __nv_bfloat16* __restrict__ xlo,
    const __nv_bfloat16* __restrict__ whi,   const __nv_bfloat16* __restrict__ wlo,
    const float* __restrict__ bias,
    __nv_bfloat16* __restrict__ outhi, __nv_bfloat16* __restrict__ outlo,  // intermediate
    float* __restrict__ foutv, float* __restrict__ tail, int final_layer)  // final
{
    extern __shared__ char smem[];
    __nv_bfloat16* BH = reinterpret_cast<__nv_bfloat16*>(smem + OFF_BH);
    __nv_bfloat16* BL = reinterpret_cast<__nv_bfloat16*>(smem + OFF_BL);
    __nv_bfloat16* BB = reinterpret_cast<__nv_bfloat16*>(smem + OFF_BB);
    __nv_bfloat16* AB = reinterpret_cast<__nv_bfloat16*>(smem + OFF_AB);
    uint32_t smemA;
    { // u32 address of A region for cp.async
        uint32_t a;
        asm("{ .reg .u64 t; cvta.to.shared.u64 t, %1; cvt.u32.u64 %0, t; }" : "=r"(a) : "l"(smem + OFF_A));
        smemA = a;
    }

    const int tid = threadIdx.x;
    const int wid = tid >> 5;
    const int wm = wid >> 2;      // 0..3 -> rows 32*wm
    const int wn = wid & 3;       // 0..3 -> cols 32*wn
    const int r = tid >> 2;       // 0..127  (A staging row)
    const int quarter = tid & 3;  // 8 bf16 = 16B each

    // one-time staging: B hi/lo, bias chunks
    #pragma unroll
    for (int j = 0; j < 8; j++) {
        int f = tid + j * 512;
        int rr = f >> 4, c8 = f & 15;
        uint4 vh = *reinterpret_cast<const uint4*>(whi + (size_t)rr * 128 + c8 * 8);
        uint4 vl = *reinterpret_cast<const uint4*>(wlo + (size_t)rr * 128 + c8 * 8);
        *reinterpret_cast<uint4*>(BH + rr * BSTR + c8 * 8) = vh;
        *reinterpret_cast<uint4*>(BL + rr * BSTR + c8 * 8) = vl;
    }
    for (int i = tid; i < (16 * BSTR + 128 * ASTR) / 2; i += 512)
        reinterpret_cast<uint32_t*>(BB)[i] = 0;  // BB then AB contiguous
    __syncthreads();
    if (tid < 128) {
        __nv_bfloat16 h, l;
        split_bf(bias[tid], h, l);
        BB[0 * BSTR + tid] = h;
        BB[1 * BSTR + tid] = l;
        AB[tid * ASTR + 0] = __float2bfloat16_rn(1.0f);
        AB[tid * ASTR + 1] = __float2bfloat16_rn(1.0f);
    }
    __syncthreads();

    for (int tile = blockIdx.x; tile < NTILES; tile += 148) {
        const int row0 = tile * 128;
        const int grow = row0 + r;
        const int sz = (grow < NN) ? 16 : 0;

        auto issue = [&](int c) {
            const __nv_bfloat16* ph = (c < 4) ? agghi : xhi;
            const __nv_bfloat16* pl = (c < 4) ? agglo : xlo;
            const int k0 = (c & 3) * 32;
            const __nv_bfloat16* sh = ph + (size_t)grow * DH + k0 + quarter * 8;
            const __nv_bfloat16* sl = pl + (size_t)grow * DH + k0 + quarter * 8;
            uint32_t dh = smemA + (uint32_t)(c % 3) * 20480u + (uint32_t)(r * ASTR + quarter * 8) * 2u;
            uint32_t dl = dh + 10240u;
            asm volatile("cp.async.cg.shared.global [%0], [%1], 16, %2;" :: "r"(dh), "l"(sh), "r"(sz));
            asm volatile("cp.async.cg.shared.global [%0], [%1], 16, %2;" :: "r"(dl), "l"(sl), "r"(sz));
            asm volatile("cp.async.commit_group;");
        };

        wmma::fragment<wmma::accumulator, 16, 16, 16, float> acc[2][2];
        #pragma unroll
        for (int i = 0; i < 2; i++)
            #pragma unroll
            for (int j = 0; j < 2; j++) wmma::fill_fragment(acc[i][j], 0.f);

        // bias rank-1 chunk
        {
            wmma::fragment<wmma::matrix_a, 16, 16, 16, __nv_bfloat16, wmma::row_major> fa[2];
            wmma::fragment<wmma::matrix_b, 16, 16, 16, __nv_bfloat16, wmma::row_major> fb[2];
            #pragma unroll
            for (int i = 0; i < 2; i++)
                wmma::load_matrix_sync(fa[i], AB + (32 * wm + 16 * i) * ASTR, ASTR);
            #pragma unroll
            for (int j = 0; j < 2; j++)
                wmma::load_matrix_sync(fb[j], BB + 32 * wn + 16 * j, BSTR);
            #pragma unroll
            for (int i = 0; i < 2; i++)
                #pragma unroll
                for (int j = 0; j < 2; j++)
                    wmma::mma_sync(acc[i][j], fa[i], fb[j], acc[i][j]);
        }

        issue(0);

        #pragma unroll 1
        for (int c = 0; c < 8; c++) {
            if (c < 7) {
                issue(c + 1);
                asm volatile("cp.async.wait_group 1;");
            } else {
                asm volatile("cp.async.wait_group 0;");
            }
            __syncthreads();
            const __nv_bfloat16* AHc = reinterpret_cast<const __nv_bfloat16*>(smem + OFF_A + (c % 3) * 20480);
            const __nv_bfloat16* ALc = AHc + 5120;   // 10240 bytes
            #pragma unroll
            for (int kk = 0; kk < 2; kk++) {
                wmma::fragment<wmma::matrix_a, 16, 16, 16, __nv_bfloat16, wmma::row_major> fah[2], fal[2];
                wmma::fragment<wmma::matrix_b, 16, 16, 16, __nv_bfloat16, wmma::row_major> fbh[2], fbl[2];
                #pragma unroll
                for (int i = 0; i < 2; i++) {
                    wmma::load_matrix_sync(fah[i], AHc + (32 * wm + 16 * i) * ASTR + kk * 16, ASTR);
                    wmma::load_matrix_sync(fal[i], ALc + (32 * wm + 16 * i) * ASTR + kk * 16, ASTR);
                }
                const int krow = c * 32 + kk * 16;
                #pragma unroll
                for (int j = 0; j < 2; j++) {
                    wmma::load_matrix_sync(fbh[j], BH + krow * BSTR + 32 * wn + 16 * j, BSTR);
                    wmma::load_matrix_sync(fbl[j], BL + krow * BSTR + 32 * wn + 16 * j, BSTR);
                }
                #pragma unroll
                for (int i = 0; i < 2; i++)
                    #pragma unroll
                    for (int j = 0; j < 2; j++) {
                        wmma::mma_sync(acc[i][j], fah[i], fbh[j], acc[i][j]);
                        wmma::mma_sync(acc[i][j], fah[i], fbl[j], acc[i][j]);
                        wmma::mma_sync(acc[i][j], fal[i], fbh[j], acc[i][j]);
                    }
            }
        }

        // relu on fragments
        #pragma unroll
        for (int i = 0; i < 2; i++)
            #pragma unroll
            for (int j = 0; j < 2; j++)
                #pragma unroll
                for (int e = 0; e < acc[i][j].num_elements; e++)
                    acc[i][j].x[e] = fmaxf(acc[i][j].x[e], 0.f);

        if (!final_layer) {
            // write hi/lo planes via smem roundtrip, 64 rows per pass (scratch = A region)
            float* scr = reinterpret_cast<float*>(smem + OFF_A);   // 64 x 132 f32 = 33792 B
            #pragma unroll 1
            for (int hh = 0; hh < 2; hh++) {
                __syncthreads();
                if ((wm >> 1) == hh) {
                    int lr = 32 * (wm & 1);
                    #pragma unroll
                    for (int i = 0; i < 2; i++)
                        #pragma unroll
                        for (int j = 0; j < 2; j++)
                            wmma::store_matrix_sync(scr + (lr + 16 * i) * 132 + 32 * wn + 16 * j,
                                                    acc[i][j], 132, wmma::mem_row_major);
                }
                __syncthreads();
                int r6 = tid >> 3;      // 0..63
                int part = tid & 7;     // 16 elems
                int gr = row0 + hh * 64 + r6;
                if (gr < NN) {
                    const float* srow = scr + r6 * 132 + part * 16;
                    uint32_t hp[8], lp[8];
                    #pragma unroll
                    for (int q = 0; q < 8; q++) {
                        __nv_bfloat16 h0, l0, h1, l1;
                        split_bf(srow[2 * q], h0, l0);
                        split_bf(srow[2 * q + 1], h1, l1);
                        hp[q] = bfpack(h0, h1);
                        lp[q] = bfpack(l0, l1);
                    }
                    size_t off = (size_t)gr * DH + part * 16;
                    *reinterpret_cast<uint4*>(outhi + off)     = *reinterpret_cast<uint4*>(hp);
                    *reinterpret_cast<uint4*>(outhi + off + 8) = *reinterpret_cast<uint4*>(hp + 4);
                    *reinterpret_cast<uint4*>(outlo + off)     = *reinterpret_cast<uint4*>(lp);
                    *reinterpret_cast<uint4*>(outlo + off + 8) = *reinterpret_cast<uint4*>(lp + 4);
                }
            }
            __syncthreads();   // scratch becomes A ring again next tile
        } else {
            if (row0 + 128 <= NN) {
                #pragma unroll
                for (int i = 0; i < 2; i++)
                    #pragma unroll
                    for (int j = 0; j < 2; j++)
                        wmma::store_matrix_sync(foutv + (size_t)(row0 + 32 * wm + 16 * i) * DH + 32 * wn + 16 * j,
                                                acc[i][j], DH, wmma::mem_row_major);
            } else {
                #pragma unroll
                for (int i = 0; i < 2; i++)
                    #pragma unroll
                    for (int j = 0; j < 2; j++)
                        wmma::store_matrix_sync(tail + (size_t)(32 * wm + 16 * i) * DH + 32 * wn + 16 * j,
                                                acc[i][j], DH, wmma::mem_row_major);
                __syncthreads();
                if (grow < NN) {
                    const float* srow = tail + (size_t)r * DH + quarter * 32;
                    float* drow = foutv + (size_t)grow * DH + quarter * 32;
                    #pragma unroll
                    for (int q = 0; q < 8; q++)
                        *reinterpret_cast<float4*>(drow + q * 4) =
                            *reinterpret_cast<const float4*>(srow + q * 4);
                }
            }
            __syncthreads();
        }
    }
}

// ============ host ============
extern "C" void kernel_launch(void* const* d_in, const int* in_sizes, int n_in,
                              void* d_out, int out_size) {
    const float* x      = (const float*)d_in[0];
    const int*   ei     = (const int*)d_in[1];
    const float* ea     = (const float*)d_in[2];
    const float* Wrel1  = (const float*)d_in[3];
    const float* b1     = (const float*)d_in[4];
    const float* Wroot1 = (const float*)d_in[5];
    const float* Wrel2  = (const float*)d_in[6];
    const float* b2     = (const float*)d_in[7];
    const float* Wroot2 = (const float*)d_in[8];
    const float* Wrel3  = (const float*)d_in[9];
    const float* b3     = (const float*)d_in[10];
    const float* Wroot3 = (const float*)d_in[11];
    float* out = (float*)d_out;

    const int* src = ei;
    const int* dst = ei + NE;

    int *deg, *rowptr, *cursor;
    uint2 *csr;
    float *tail;
    __nv_bfloat16 *agghi, *agglo, *xhi, *xlo, *h1hi, *h1lo, *h2hi, *h2lo, *whi, *wlo;
    cudaGetSymbolAddress((void**)&deg,    g_deg);
    cudaGetSymbolAddress((void**)&rowptr, g_rowptr);
    cudaGetSymbolAddress((void**)&cursor, g_cursor);
    cudaGetSymbolAddress((void**)&csr,    g_csr);
    cudaGetSymbolAddress((void**)&agghi,  g_agghi);
    cudaGetSymbolAddress((void**)&agglo,  g_agglo);
    cudaGetSymbolAddress((void**)&xhi,    g_xhi);
    cudaGetSymbolAddress((void**)&xlo,    g_xlo);
    cudaGetSymbolAddress((void**)&h1hi,   g_h1hi);
    cudaGetSymbolAddress((void**)&h1lo,   g_h1lo);
    cudaGetSymbolAddress((void**)&h2hi,   g_h2hi);
    cudaGetSymbolAddress((void**)&h2lo,   g_h2lo);
    cudaGetSymbolAddress((void**)&tail,   g_tail);
    cudaGetSymbolAddress((void**)&whi,    g_whi);
    cudaGetSymbolAddress((void**)&wlo,    g_wlo);

    cudaFuncSetAttribute(gemm_persist_kernel,
                         cudaFuncAttributeMaxDynamicSharedMemorySize, GEMM_SMEM);

    // CSR build + splits (once)
    cudaMemsetAsync(deg, 0, NN * sizeof(int));
    deg_count_kernel<<<(NE + 255) / 256, 256>>>(dst, deg);
    scan_kernel<<<1, 1024>>>(deg, rowptr, cursor);
    fill_csr_kernel<<<(NE + 255) / 256, 256>>>(src, dst, ea, cursor, csr);
    split_x_kernel<<<(NN * DH / 4 + 255) / 256, 256>>>(x, xhi, xlo);
    prep_w_kernel<<<(3 * 256 * 128 + 255) / 256, 256>>>(Wrel1, Wroot1, Wrel2, Wroot2, Wrel3, Wroot3, whi, wlo);

    const __nv_bfloat16* inhi[3] = {xhi, h1hi, h2hi};
    const __nv_bfloat16* inlo[3] = {xlo, h1lo, h2lo};
    __nv_bfloat16* ohi[3] = {h1hi, h2hi, nullptr};
    __nv_bfloat16* olo[3] = {h1lo, h2lo, nullptr};
    const float* bv[3] = {b1, b2, b3};

    int gather_blocks = (NN * 32 + 255) / 256;
    for (int l = 0; l < 3; l++) {
        gather_agg_kernel<<<gather_blocks, 256>>>(inhi[l], inlo[l], rowptr, csr, agghi, agglo);
        gemm_persist_kernel<<<148, 512, GEMM_SMEM>>>(
            agghi, agglo, inhi[l], inlo[l],
            whi + l * 32768, wlo + l * 32768, bv[l],
            ohi[l], olo[l], out, tail, l == 2 ? 1 : 0);
    }
}